// round 1
// baseline (speedup 1.0000x reference)
#include <cuda_runtime.h>
#include <math.h>

// Problem constants (B=2, N=4096, C=256, K=64; hidden = 256, out = 256)
#define PB 2
#define PN 4096
#define PC 256
#define PK 64
#define THREADS 256

__global__ __launch_bounds__(THREADS)
void roi_fused_kernel(const float* __restrict__ points,        // (B, N, 3)
                      const float* __restrict__ feats,         // (B, N, C)
                      const float* __restrict__ props,         // (B, K, 7)
                      const float* __restrict__ W1,            // (C, 256)
                      const float* __restrict__ b1,            // (256)
                      const float* __restrict__ W2,            // (256, 256)
                      const float* __restrict__ b2,            // (256)
                      float* __restrict__ out)                 // (B, K, 256)
{
    const int bk = blockIdx.x;          // 0 .. B*K-1
    const int b  = bk / PK;
    const int t  = threadIdx.x;         // channel / output index

    __shared__ int   s_idx[PN];
    __shared__ int   s_count;
    __shared__ float s_box[6];
    __shared__ float s_vec[PC];

    if (t == 0) s_count = 0;
    if (t < 3) {
        float c = props[bk * 7 + t];
        float h = props[bk * 7 + 3 + t] * 0.5f;
        s_box[t]     = c - h;   // lo
        s_box[t + 3] = c + h;   // hi
    }
    __syncthreads();

    const float lx = s_box[0], ly = s_box[1], lz = s_box[2];
    const float hx = s_box[3], hy = s_box[4], hz = s_box[5];

    // Phase 1: compact indices of points strictly inside the box
    const float* pb = points + (size_t)b * PN * 3;
    #pragma unroll 4
    for (int n = t; n < PN; n += THREADS) {
        float px = pb[n * 3 + 0];
        float py = pb[n * 3 + 1];
        float pz = pb[n * 3 + 2];
        bool inside = (px > lx) & (px < hx) &
                      (py > ly) & (py < hy) &
                      (pz > lz) & (pz < hz);
        if (inside) {
            int pos = atomicAdd(&s_count, 1);
            s_idx[pos] = n;
        }
    }
    __syncthreads();
    const int cnt = s_count;

    // Phase 2: max-pool features over inside points (thread t = channel t)
    float acc = -INFINITY;
    const float* fb = feats + (size_t)b * PN * PC;
    int i = 0;
    for (; i + 4 <= cnt; i += 4) {
        int n0 = s_idx[i + 0];
        int n1 = s_idx[i + 1];
        int n2 = s_idx[i + 2];
        int n3 = s_idx[i + 3];
        float v0 = fb[(size_t)n0 * PC + t];
        float v1 = fb[(size_t)n1 * PC + t];
        float v2 = fb[(size_t)n2 * PC + t];
        float v3 = fb[(size_t)n3 * PC + t];
        acc = fmaxf(acc, fmaxf(fmaxf(v0, v1), fmaxf(v2, v3)));
    }
    for (; i < cnt; i++) {
        acc = fmaxf(acc, fb[(size_t)s_idx[i] * PC + t]);
    }
    if (cnt == 0) acc = 0.0f;   // reference: zero when no point falls inside

    s_vec[t] = acc;
    __syncthreads();

    // Phase 3: h = relu(pooled @ W1 + b1)   (thread t computes output d = t)
    float hacc = b1[t];
    #pragma unroll 8
    for (int c = 0; c < PC; c++) {
        hacc = fmaf(s_vec[c], W1[c * 256 + t], hacc);
    }
    hacc = fmaxf(hacc, 0.0f);
    __syncthreads();            // everyone done reading s_vec
    s_vec[t] = hacc;
    __syncthreads();

    // Phase 4: out = relu(h @ W2 + b2)
    float oacc = b2[t];
    #pragma unroll 8
    for (int c = 0; c < 256; c++) {
        oacc = fmaf(s_vec[c], W2[c * 256 + t], oacc);
    }
    oacc = fmaxf(oacc, 0.0f);

    out[(size_t)bk * 256 + t] = oacc;
}

extern "C" void kernel_launch(void* const* d_in, const int* in_sizes, int n_in,
                              void* d_out, int out_size)
{
    const float* points = (const float*)d_in[0];   // (B, N, 3)
    const float* feats  = (const float*)d_in[1];   // (B, N, C)
    const float* props  = (const float*)d_in[2];   // (B, K, 7)
    const float* W1     = (const float*)d_in[3];   // (C, 256)
    const float* b1     = (const float*)d_in[4];   // (256)
    const float* W2     = (const float*)d_in[5];   // (256, 256)
    const float* b2     = (const float*)d_in[6];   // (256)
    float*       out    = (float*)d_out;           // (B, K, 256)

    roi_fused_kernel<<<PB * PK, THREADS>>>(points, feats, props, W1, b1, W2, b2, out);
}

// round 2
// speedup vs baseline: 1.8393x; 1.8393x over previous
#include <cuda_runtime.h>
#include <math.h>

// Problem constants (B=2, N=4096, C=256, K=64; hidden = 256, out = 256)
#define PB 2
#define PN 4096
#define PC 256
#define PK 64
#define THREADS 1024
#define SLICES 4            // THREADS / 256

__global__ __launch_bounds__(THREADS)
void roi_fused_kernel(const float* __restrict__ points,        // (B, N, 3)
                      const float* __restrict__ feats,         // (B, N, C)
                      const float* __restrict__ props,         // (B, K, 7)
                      const float* __restrict__ W1,            // (C, 256)
                      const float* __restrict__ b1,            // (256)
                      const float* __restrict__ W2,            // (256, 256)
                      const float* __restrict__ b2,            // (256)
                      float* __restrict__ out)                 // (B, K, 256)
{
    const int bk = blockIdx.x;          // 0 .. B*K-1
    const int b  = bk / PK;
    const int t  = threadIdx.x;
    const int ch = t & 255;             // channel / output neuron
    const int sl = t >> 8;              // slice 0..3

    __shared__ int   s_idx[PN];
    __shared__ int   s_count;
    __shared__ float s_box[6];
    __shared__ float s_part[SLICES * 256];
    __shared__ float s_vec[256];        // pooled features
    __shared__ float s_h[256];          // hidden activations

    if (t == 0) s_count = 0;
    if (t < 3) {
        float c = props[bk * 7 + t];
        float h = props[bk * 7 + 3 + t] * 0.5f;
        s_box[t]     = c - h;   // lo
        s_box[t + 3] = c + h;   // hi
    }
    __syncthreads();

    const float lx = s_box[0], ly = s_box[1], lz = s_box[2];
    const float hx = s_box[3], hy = s_box[4], hz = s_box[5];

    // ---- Phase 1: compact indices of points strictly inside the box ----
    const float* pb = points + (size_t)b * PN * 3;
    #pragma unroll 4
    for (int n = t; n < PN; n += THREADS) {
        float px = pb[n * 3 + 0];
        float py = pb[n * 3 + 1];
        float pz = pb[n * 3 + 2];
        bool inside = (px > lx) & (px < hx) &
                      (py > ly) & (py < hy) &
                      (pz > lz) & (pz < hz);
        if (inside) {
            int pos = atomicAdd(&s_count, 1);
            s_idx[pos] = n;
        }
    }
    __syncthreads();
    const int cnt = s_count;

    // ---- Phase 2: max-pool; 4 slices each take a strided quarter ----
    float acc = -INFINITY;
    const float* fb = feats + (size_t)b * PN * PC;
    {
        int i = sl;
        // 4 independent loads in flight per thread
        for (; i + 3 * SLICES < cnt; i += 4 * SLICES) {
            int n0 = s_idx[i + 0 * SLICES];
            int n1 = s_idx[i + 1 * SLICES];
            int n2 = s_idx[i + 2 * SLICES];
            int n3 = s_idx[i + 3 * SLICES];
            float v0 = fb[(size_t)n0 * PC + ch];
            float v1 = fb[(size_t)n1 * PC + ch];
            float v2 = fb[(size_t)n2 * PC + ch];
            float v3 = fb[(size_t)n3 * PC + ch];
            acc = fmaxf(acc, fmaxf(fmaxf(v0, v1), fmaxf(v2, v3)));
        }
        for (; i < cnt; i += SLICES) {
            acc = fmaxf(acc, fb[(size_t)s_idx[i] * PC + ch]);
        }
    }
    s_part[sl * 256 + ch] = acc;
    __syncthreads();

    if (t < 256) {
        float m = fmaxf(fmaxf(s_part[t], s_part[256 + t]),
                        fmaxf(s_part[512 + t], s_part[768 + t]));
        s_vec[t] = (cnt == 0) ? 0.0f : m;
    }
    __syncthreads();

    // ---- Phase 3: h = relu(pooled @ W1 + b1); 4 threads per neuron ----
    {
        float hp = 0.0f;
        const int c0 = sl * 64;
        #pragma unroll 8
        for (int c = 0; c < 64; c++) {
            hp = fmaf(s_vec[c0 + c], W1[(c0 + c) * 256 + ch], hp);
        }
        s_part[sl * 256 + ch] = hp;
    }
    __syncthreads();
    if (t < 256) {
        float h = s_part[t] + s_part[256 + t] + s_part[512 + t] + s_part[768 + t] + b1[t];
        s_h[t] = fmaxf(h, 0.0f);
    }
    __syncthreads();

    // ---- Phase 4: out = relu(h @ W2 + b2); 4 threads per neuron ----
    {
        float op = 0.0f;
        const int c0 = sl * 64;
        #pragma unroll 8
        for (int c = 0; c < 64; c++) {
            op = fmaf(s_h[c0 + c], W2[(c0 + c) * 256 + ch], op);
        }
        s_part[sl * 256 + ch] = op;
    }
    __syncthreads();
    if (t < 256) {
        float o = s_part[t] + s_part[256 + t] + s_part[512 + t] + s_part[768 + t] + b2[t];
        out[(size_t)bk * 256 + t] = fmaxf(o, 0.0f);
    }
}

extern "C" void kernel_launch(void* const* d_in, const int* in_sizes, int n_in,
                              void* d_out, int out_size)
{
    const float* points = (const float*)d_in[0];   // (B, N, 3)
    const float* feats  = (const float*)d_in[1];   // (B, N, C)
    const float* props  = (const float*)d_in[2];   // (B, K, 7)
    const float* W1     = (const float*)d_in[3];   // (C, 256)
    const float* b1     = (const float*)d_in[4];   // (256)
    const float* W2     = (const float*)d_in[5];   // (256, 256)
    const float* b2     = (const float*)d_in[6];   // (256)
    float*       out    = (float*)d_out;           // (B, K, 256)

    roi_fused_kernel<<<PB * PK, THREADS>>>(points, feats, props, W1, b1, W2, b2, out);
}

// round 3
// speedup vs baseline: 2.3768x; 1.2923x over previous
#include <cuda_runtime.h>
#include <math.h>

// Problem constants (B=2, N=4096, C=256, K=64; hidden = 256, out = 256)
#define PB 2
#define PN 4096
#define PC 256
#define PK 64
#define THREADS 1024
#define NSL 16              // slices; THREADS / 64 quads

__global__ __launch_bounds__(THREADS)
void roi_fused_kernel(const float* __restrict__ points,        // (B, N, 3)
                      const float* __restrict__ feats,         // (B, N, C)
                      const float* __restrict__ props,         // (B, K, 7)
                      const float* __restrict__ W1,            // (C, 256)
                      const float* __restrict__ b1,            // (256)
                      const float* __restrict__ W2,            // (256, 256)
                      const float* __restrict__ b2,            // (256)
                      float* __restrict__ out)                 // (B, K, 256)
{
    const int bk = blockIdx.x;          // 0 .. B*K-1
    const int b  = bk / PK;
    const int t  = threadIdx.x;
    const int q  = t & 63;              // channel-quad index (4 channels each)
    const int sl = t >> 6;              // slice 0..15

    __shared__ int    s_idx[PN];
    __shared__ int    s_count;
    __shared__ float  s_box[6];
    __shared__ float4 s_part[THREADS];  // 16 KB reduction scratch
    __shared__ float4 s_vec[64];        // pooled features (256 floats)
    __shared__ float4 s_h[64];          // hidden activations

    if (t == 0) s_count = 0;
    if (t < 3) {
        float c = props[bk * 7 + t];
        float h = props[bk * 7 + 3 + t] * 0.5f;
        s_box[t]     = c - h;   // lo
        s_box[t + 3] = c + h;   // hi
    }
    __syncthreads();

    const float lx = s_box[0], ly = s_box[1], lz = s_box[2];
    const float hx = s_box[3], hy = s_box[4], hz = s_box[5];

    // ---- Phase 1: compact indices of points strictly inside the box ----
    const float* pb = points + (size_t)b * PN * 3;
    #pragma unroll 4
    for (int n = t; n < PN; n += THREADS) {
        float px = pb[n * 3 + 0];
        float py = pb[n * 3 + 1];
        float pz = pb[n * 3 + 2];
        bool inside = (px > lx) & (px < hx) &
                      (py > ly) & (py < hy) &
                      (pz > lz) & (pz < hz);
        if (inside) {
            int pos = atomicAdd(&s_count, 1);
            s_idx[pos] = n;
        }
    }
    __syncthreads();
    const int cnt = s_count;

    // ---- Phase 2: max-pool; 16 slices stride the inside list, float4 lanes ----
    const float4* fb4 = (const float4*)(feats + (size_t)b * PN * PC);
    float4 acc = make_float4(-INFINITY, -INFINITY, -INFINITY, -INFINITY);
    {
        int i = sl;
        for (; i + 3 * NSL < cnt; i += 4 * NSL) {
            int n0 = s_idx[i + 0 * NSL];
            int n1 = s_idx[i + 1 * NSL];
            int n2 = s_idx[i + 2 * NSL];
            int n3 = s_idx[i + 3 * NSL];
            float4 v0 = fb4[(size_t)n0 * 64 + q];
            float4 v1 = fb4[(size_t)n1 * 64 + q];
            float4 v2 = fb4[(size_t)n2 * 64 + q];
            float4 v3 = fb4[(size_t)n3 * 64 + q];
            acc.x = fmaxf(acc.x, fmaxf(fmaxf(v0.x, v1.x), fmaxf(v2.x, v3.x)));
            acc.y = fmaxf(acc.y, fmaxf(fmaxf(v0.y, v1.y), fmaxf(v2.y, v3.y)));
            acc.z = fmaxf(acc.z, fmaxf(fmaxf(v0.z, v1.z), fmaxf(v2.z, v3.z)));
            acc.w = fmaxf(acc.w, fmaxf(fmaxf(v0.w, v1.w), fmaxf(v2.w, v3.w)));
        }
        for (; i < cnt; i += NSL) {
            float4 v = fb4[(size_t)s_idx[i] * 64 + q];
            acc.x = fmaxf(acc.x, v.x);
            acc.y = fmaxf(acc.y, v.y);
            acc.z = fmaxf(acc.z, v.z);
            acc.w = fmaxf(acc.w, v.w);
        }
    }
    s_part[t] = acc;
    __syncthreads();

    // reduce 16 slices -> 4 -> 1 (max)
    if (t < 256) {
        int g = t >> 6, qq = t & 63;
        float4 a = s_part[(g + 0) * 64 + qq];
        float4 c1 = s_part[(g + 4) * 64 + qq];
        float4 c2 = s_part[(g + 8) * 64 + qq];
        float4 c3 = s_part[(g + 12) * 64 + qq];
        a.x = fmaxf(fmaxf(a.x, c1.x), fmaxf(c2.x, c3.x));
        a.y = fmaxf(fmaxf(a.y, c1.y), fmaxf(c2.y, c3.y));
        a.z = fmaxf(fmaxf(a.z, c1.z), fmaxf(c2.z, c3.z));
        a.w = fmaxf(fmaxf(a.w, c1.w), fmaxf(c2.w, c3.w));
        s_part[g * 64 + qq] = a;
    }
    __syncthreads();
    if (t < 64) {
        float4 a  = s_part[t];
        float4 c1 = s_part[64 + t];
        float4 c2 = s_part[128 + t];
        float4 c3 = s_part[192 + t];
        a.x = fmaxf(fmaxf(a.x, c1.x), fmaxf(c2.x, c3.x));
        a.y = fmaxf(fmaxf(a.y, c1.y), fmaxf(c2.y, c3.y));
        a.z = fmaxf(fmaxf(a.z, c1.z), fmaxf(c2.z, c3.z));
        a.w = fmaxf(fmaxf(a.w, c1.w), fmaxf(c2.w, c3.w));
        if (cnt == 0) a = make_float4(0.f, 0.f, 0.f, 0.f);
        s_vec[t] = a;
    }
    __syncthreads();

    // ---- Phase 3: h = relu(pooled @ W1 + b1); slice sl covers c in [16*sl, 16*sl+16) ----
    {
        const float4* W1_4 = (const float4*)W1;
        const float*  vecf = (const float*)s_vec;
        float4 ha = make_float4(0.f, 0.f, 0.f, 0.f);
        const int c0 = sl * 16;
        #pragma unroll
        for (int c = 0; c < 16; c++) {
            float f = vecf[c0 + c];                  // warp-uniform broadcast
            float4 w = W1_4[(size_t)(c0 + c) * 64 + q];
            ha.x = fmaf(f, w.x, ha.x);
            ha.y = fmaf(f, w.y, ha.y);
            ha.z = fmaf(f, w.z, ha.z);
            ha.w = fmaf(f, w.w, ha.w);
        }
        s_part[t] = ha;
    }
    __syncthreads();
    if (t < 256) {
        int g = t >> 6, qq = t & 63;
        float4 a  = s_part[(g + 0) * 64 + qq];
        float4 c1 = s_part[(g + 4) * 64 + qq];
        float4 c2 = s_part[(g + 8) * 64 + qq];
        float4 c3 = s_part[(g + 12) * 64 + qq];
        a.x += c1.x + c2.x + c3.x;
        a.y += c1.y + c2.y + c3.y;
        a.z += c1.z + c2.z + c3.z;
        a.w += c1.w + c2.w + c3.w;
        s_part[g * 64 + qq] = a;
    }
    __syncthreads();
    if (t < 64) {
        float4 a  = s_part[t];
        float4 c1 = s_part[64 + t];
        float4 c2 = s_part[128 + t];
        float4 c3 = s_part[192 + t];
        float4 bb = ((const float4*)b1)[t];
        a.x = fmaxf(a.x + c1.x + c2.x + c3.x + bb.x, 0.f);
        a.y = fmaxf(a.y + c1.y + c2.y + c3.y + bb.y, 0.f);
        a.z = fmaxf(a.z + c1.z + c2.z + c3.z + bb.z, 0.f);
        a.w = fmaxf(a.w + c1.w + c2.w + c3.w + bb.w, 0.f);
        s_h[t] = a;
    }
    __syncthreads();

    // ---- Phase 4: out = relu(h @ W2 + b2) ----
    {
        const float4* W2_4 = (const float4*)W2;
        const float*  hf = (const float*)s_h;
        float4 oa = make_float4(0.f, 0.f, 0.f, 0.f);
        const int c0 = sl * 16;
        #pragma unroll
        for (int c = 0; c < 16; c++) {
            float f = hf[c0 + c];
            float4 w = W2_4[(size_t)(c0 + c) * 64 + q];
            oa.x = fmaf(f, w.x, oa.x);
            oa.y = fmaf(f, w.y, oa.y);
            oa.z = fmaf(f, w.z, oa.z);
            oa.w = fmaf(f, w.w, oa.w);
        }
        s_part[t] = oa;
    }
    __syncthreads();
    if (t < 256) {
        int g = t >> 6, qq = t & 63;
        float4 a  = s_part[(g + 0) * 64 + qq];
        float4 c1 = s_part[(g + 4) * 64 + qq];
        float4 c2 = s_part[(g + 8) * 64 + qq];
        float4 c3 = s_part[(g + 12) * 64 + qq];
        a.x += c1.x + c2.x + c3.x;
        a.y += c1.y + c2.y + c3.y;
        a.z += c1.z + c2.z + c3.z;
        a.w += c1.w + c2.w + c3.w;
        s_part[g * 64 + qq] = a;
    }
    __syncthreads();
    if (t < 64) {
        float4 a  = s_part[t];
        float4 c1 = s_part[64 + t];
        float4 c2 = s_part[128 + t];
        float4 c3 = s_part[192 + t];
        float4 bb = ((const float4*)b2)[t];
        a.x = fmaxf(a.x + c1.x + c2.x + c3.x + bb.x, 0.f);
        a.y = fmaxf(a.y + c1.y + c2.y + c3.y + bb.y, 0.f);
        a.z = fmaxf(a.z + c1.z + c2.z + c3.z + bb.z, 0.f);
        a.w = fmaxf(a.w + c1.w + c2.w + c3.w + bb.w, 0.f);
        ((float4*)out)[(size_t)bk * 64 + t] = a;
    }
}

extern "C" void kernel_launch(void* const* d_in, const int* in_sizes, int n_in,
                              void* d_out, int out_size)
{
    const float* points = (const float*)d_in[0];   // (B, N, 3)
    const float* feats  = (const float*)d_in[1];   // (B, N, C)
    const float* props  = (const float*)d_in[2];   // (B, K, 7)
    const float* W1     = (const float*)d_in[3];   // (C, 256)
    const float* b1     = (const float*)d_in[4];   // (256)
    const float* W2     = (const float*)d_in[5];   // (256, 256)
    const float* b2     = (const float*)d_in[6];   // (256)
    float*       out    = (float*)d_out;           // (B, K, 256)

    roi_fused_kernel<<<PB * PK, THREADS>>>(points, feats, props, W1, b1, W2, b2, out);
}